// round 15
// baseline (speedup 1.0000x reference)
#include <cuda_runtime.h>
#include <cuda_fp16.h>
#include <cstdint>

#define T_DIM 4
#define N_DIM 32
#define C_DIM 512
#define L_DIM 196
#define H_DIM 8
#define D_DIM 64
#define C3 (3 * C_DIM)
#define B_DIM (T_DIM * N_DIM)     // 128
#define K_DIM 512
#define NCOL (B_DIM * L_DIM)      // 25088
#define TSTRIDE (N_DIM * L_DIM)   // 6272 = 196 * 32

// ---------------------------------------------------------------------------
// Scratch (device globals)
// ---------------------------------------------------------------------------
__device__ __half        g_xh   [(size_t)K_DIM * NCOL];
__device__ __half        g_wq   [(size_t)C3 * 1024];
__device__ __half        g_wp   [(size_t)C_DIM * 1024];
__device__ unsigned char g_qkvb [(size_t)C3 * NCOL];    // qkv spikes u8
__device__ __half        g_attnp[(size_t)C_DIM * NCOL]; // pre-LIF attn (fp16, exact)
__device__ __half        g_attnh[(size_t)C_DIM * NCOL]; // attn spikes fp16

// ---------------------------------------------------------------------------
// PTX helpers
// ---------------------------------------------------------------------------
__device__ __forceinline__ uint32_t smem_u32(const void* p) {
    return (uint32_t)__cvta_generic_to_shared(p);
}
__device__ __forceinline__ void cp_async16(uint32_t dst, const void* src) {
    asm volatile("cp.async.cg.shared.global [%0], [%1], 16;\n" :: "r"(dst), "l"(src));
}
__device__ __forceinline__ void cp_commit() {
    asm volatile("cp.async.commit_group;\n");
}
__device__ __forceinline__ void ldsm4(uint32_t (&r)[4], uint32_t addr) {
    asm volatile("ldmatrix.sync.aligned.m8n8.x4.shared.b16 {%0,%1,%2,%3}, [%4];"
                 : "=r"(r[0]), "=r"(r[1]), "=r"(r[2]), "=r"(r[3]) : "r"(addr));
}
__device__ __forceinline__ void ldsm4t(uint32_t (&r)[4], uint32_t addr) {
    asm volatile("ldmatrix.sync.aligned.m8n8.x4.trans.shared.b16 {%0,%1,%2,%3}, [%4];"
                 : "=r"(r[0]), "=r"(r[1]), "=r"(r[2]), "=r"(r[3]) : "r"(addr));
}
__device__ __forceinline__ void mma16816(float* d, const uint32_t* a, const uint32_t* b) {
    asm volatile("mma.sync.aligned.m16n8k16.row.col.f32.f16.f16.f32 "
                 "{%0,%1,%2,%3}, {%4,%5,%6,%7}, {%8,%9}, {%0,%1,%2,%3};"
                 : "+f"(d[0]), "+f"(d[1]), "+f"(d[2]), "+f"(d[3])
                 : "r"(a[0]), "r"(a[1]), "r"(a[2]), "r"(a[3]), "r"(b[0]), "r"(b[1]));
}
__device__ __forceinline__ void imma16832(int* c, const uint32_t* a, uint32_t b0, uint32_t b1) {
    asm volatile("mma.sync.aligned.m16n8k32.row.col.s32.u8.u8.s32 "
                 "{%0,%1,%2,%3}, {%4,%5,%6,%7}, {%8,%9}, {%0,%1,%2,%3};"
                 : "+r"(c[0]), "+r"(c[1]), "+r"(c[2]), "+r"(c[3])
                 : "r"(a[0]), "r"(a[1]), "r"(a[2]), "r"(a[3]), "r"(b0), "r"(b1));
}

// ---------------------------------------------------------------------------
// Conversions
// ---------------------------------------------------------------------------
__global__ void convert_x_kernel(const float4* __restrict__ x4, uint2* __restrict__ xh4) {
    const int L4 = L_DIM / 4;                      // 49
    const size_t total = (size_t)B_DIM * K_DIM * L4;
    size_t i = (size_t)blockIdx.x * blockDim.x + threadIdx.x;
    if (i >= total) return;
    const int l4 = (int)(i % L4);
    const int c  = (int)((i / L4) % K_DIM);
    const int b  = (int)(i / ((size_t)L4 * K_DIM));
    const float4 v = x4[i];
    const __half2 h01 = __floats2half2_rn(v.x, v.y);
    const __half2 h23 = __floats2half2_rn(v.z, v.w);
    uint2 o;
    o.x = *(const uint32_t*)&h01;
    o.y = *(const uint32_t*)&h23;
    xh4[((size_t)c * NCOL + b * L_DIM) / 4 + l4] = o;
}

// Merged W split for both weight matrices.
// Ws[o][(k/32)*64 + k%32] = hi, +32 = lo (hi + lo == W exactly in f32)
__global__ void convert_w_kernel(const float* __restrict__ wq, __half* __restrict__ wsq,
                                 const float* __restrict__ wp, __half* __restrict__ wsp) {
    int i = blockIdx.x * blockDim.x + threadIdx.x;
    const float* w; __half* ws;
    if (i < C3 * K_DIM) { w = wq; ws = wsq; }
    else {
        i -= C3 * K_DIM;
        if (i >= C_DIM * K_DIM) return;
        w = wp; ws = wsp;
    }
    const int k = i & (K_DIM - 1), o = i >> 9;
    const float v = w[i];
    const __half hi = __float2half(v);
    const __half lo = __float2half(v - __half2float(hi));
    const size_t base = (size_t)o * 1024 + (k >> 5) * 64 + (k & 31);
    ws[base] = hi;
    ws[base + 32] = lo;
}

// ---------------------------------------------------------------------------
// Fused tensor-core GEMM + BN + LIF (proven configuration).
// CTA tile: 128(M) x [32 elements x 4 timesteps](N) x 32(K), 256 threads,
// 8 warps each 32m x 64n. 2 CTAs/SM. STG=4, wait_group 2.
// ---------------------------------------------------------------------------
#define OT 128
#define KT 32
#define NSTAGE 16
#define STG 4
#define STG_BYTES (OT * 128 + 2 * KT * 128)   // 24576
#define DYN_SMEM (STG * STG_BYTES)            // 98304

template <int MODE>
__global__ __launch_bounds__(256, 2) void gemm_fused_kernel(
    const __half* __restrict__ Wsp,
    const __half* __restrict__ X,
    const float* __restrict__ gamma, const float* __restrict__ beta,
    const float* __restrict__ mean,  const float* __restrict__ var,
    unsigned char* __restrict__ outB, float* __restrict__ outF)
{
    extern __shared__ __half sm[];
    const uint32_t sBase = smem_u32(sm);

    const int o0 = blockIdx.y * OT;
    const int c0 = blockIdx.x * 32;
    const int tid  = threadIdx.x;
    const int warp = tid >> 5, lane = tid & 31;
    const int wm = warp & 3, wn = warp >> 2;

    const int wrow = tid >> 1;
    const int wcb  = (tid & 1) * 4;
    const int xrow = tid >> 3;
    const int xq   = tid & 7;

    float acc[2][8][4];
#pragma unroll
    for (int a = 0; a < 2; a++)
#pragma unroll
        for (int n = 0; n < 8; n++)
#pragma unroll
            for (int j = 0; j < 4; j++) acc[a][n][j] = 0.f;

    auto issue = [&](int s) {
        const uint32_t sb = sBase + (uint32_t)(s & (STG - 1)) * STG_BYTES;
        const __half* wsrc = Wsp + (size_t)(o0 + wrow) * 1024 + s * 64;
        const uint32_t wdst = sb + wrow * 128;
#pragma unroll
        for (int i = 0; i < 4; i++) {
            int ch = wcb + i;
            cp_async16(wdst + ((ch ^ (wrow & 7)) << 4), wsrc + ch * 8);
        }
#pragma unroll
        for (int cc = 0; cc < 2; cc++) {
            const int c = xq + cc * 8;
            const __half* xsrc = X + (size_t)(s * KT + xrow) * NCOL +
                                 (size_t)(c >> 2) * TSTRIDE + c0 + (c & 3) * 8;
            const uint32_t xdst = sb + OT * 128 + (c >> 3) * 4096 + xrow * 128 +
                                  (((c & 7) ^ (xrow & 7)) << 4);
            cp_async16(xdst, xsrc);
        }
        cp_commit();
    };

    issue(0); issue(1); issue(2);

    const int lrow = lane & 15;
    const int lch  = lane >> 4;

#pragma unroll
    for (int s = 0; s < NSTAGE; s++) {
        const int rem = NSTAGE - 1 - s;
        if (rem >= 2)      asm volatile("cp.async.wait_group 2;\n");
        else if (rem == 1) asm volatile("cp.async.wait_group 1;\n");
        else               asm volatile("cp.async.wait_group 0;\n");
        __syncthreads();

        if (s + 3 < NSTAGE) issue(s + 3);

        const uint32_t sWb = sBase + (uint32_t)(s & (STG - 1)) * STG_BYTES;
        const uint32_t sXb = sWb + OT * 128 + wn * 4096;

#pragma unroll
        for (int s2 = 0; s2 < 2; s2++) {
            uint32_t Bf[4][4];
#pragma unroll
            for (int i = 0; i < 4; i++) {
                int rowB = s2 * 16 + lrow;
                int ch = i * 2 + lch;
                ldsm4t(Bf[i], sXb + rowB * 128 + ((ch ^ (rowB & 7)) << 4));
            }
#pragma unroll
            for (int p = 0; p < 2; p++) {
                uint32_t Af[2][4];
                const int kcol = p * 32 + s2 * 16;
#pragma unroll
                for (int mf = 0; mf < 2; mf++) {
                    int m = wm * 32 + mf * 16 + lrow;
                    int ch = (kcol >> 3) + lch;
                    ldsm4(Af[mf], sWb + m * 128 + ((ch ^ (m & 7)) << 4));
                }
#pragma unroll
                for (int mf = 0; mf < 2; mf++)
#pragma unroll
                    for (int nf = 0; nf < 8; nf++)
                        mma16816(acc[mf][nf], Af[mf], &Bf[nf >> 1][(nf & 1) * 2]);
            }
        }
    }

    // ---- Epilogue: BN -> smem bounce -> LIF over t -> store ----
    __syncthreads();
    float* smf = (float*)sm;   // [128][132]

#pragma unroll
    for (int mf = 0; mf < 2; mf++) {
#pragma unroll
        for (int dd = 0; dd < 2; dd++) {
            const int m = wm * 32 + mf * 16 + dd * 8 + (lane >> 2);
            const int o = o0 + m;
            const float inv  = __ldg(&gamma[o]) * rsqrtf(__ldg(&var[o]) + 1e-5f);
            const float bias = __ldg(&beta[o]) - __ldg(&mean[o]) * inv;
#pragma unroll
            for (int nf = 0; nf < 8; nf++) {
                const int j = wn * 64 + nf * 8 + (lane & 3) * 2;
                smf[m * 132 + j]     = acc[mf][nf][dd * 2 + 0] * inv + bias;
                smf[m * 132 + j + 1] = acc[mf][nf][dd * 2 + 1] * inv + bias;
            }
        }
    }
    __syncthreads();

    const int e = tid & 31;
#pragma unroll 1
    for (int pass = 0; pass < 16; pass++) {
        const int m = pass * 8 + (tid >> 5);
        const float* r = &smf[m * 132];
        float v = 0.f;
        if (MODE == 0) {
            unsigned char* dst = outB + (size_t)(o0 + m) * NCOL + c0 + e;
#pragma unroll
            for (int t = 0; t < T_DIM; t++) {
                const float x = r[t * 32 + e];
                v += 0.5f * (x - v);
                const float s = (v >= 1.0f) ? 1.f : 0.f;
                dst[(size_t)t * TSTRIDE] = (unsigned char)s;
                v *= (1.f - s);
            }
        } else {
            const int g = c0 + e;
            const int n = g / L_DIM, l = g - n * L_DIM;
#pragma unroll
            for (int t = 0; t < T_DIM; t++) {
                const float x = r[t * 32 + e];
                v += 0.5f * (x - v);
                const float s = (v >= 1.0f) ? 1.f : 0.f;
                outF[(((size_t)(t * N_DIM + n)) * C_DIM + (o0 + m)) * L_DIM + l] = s;
                v *= (1.f - s);
            }
        }
    }
}

// ---------------------------------------------------------------------------
// LIF (decay 0.5, thr 0.5) for attn: fp16 pre-LIF in (exact), fp16 spikes out.
// ---------------------------------------------------------------------------
__global__ void lif_mat_kernel(const __half2* __restrict__ in, __half2* __restrict__ out,
                               int total2, float thr)
{
    const int i = blockIdx.x * blockDim.x + threadIdx.x;
    if (i >= total2) return;
    const int half_ts = TSTRIDE / 2;
    const int o = i / half_ts, r = i % half_ts;
    const size_t base2 = ((size_t)o * NCOL) / 2 + r;
    float v0 = 0.f, v1 = 0.f;
#pragma unroll
    for (int t = 0; t < T_DIM; t++) {
        const float2 x = __half22float2(in[base2 + (size_t)t * half_ts]);
        v0 += 0.5f * (x.x - v0);
        v1 += 0.5f * (x.y - v1);
        const float s0 = (v0 >= thr) ? 1.f : 0.f;
        const float s1 = (v1 >= thr) ? 1.f : 0.f;
        out[base2 + (size_t)t * half_ts] = __floats2half2_rn(s0, s1);
        v0 *= (1.f - s0);
        v1 *= (1.f - s1);
    }
}

// ---------------------------------------------------------------------------
// Attention per (t, n, h) on int8 tensor cores. Phase-1 operand fragments are
// gathered DIRECTLY from global memory (u8 spikes; masked to 0 in the K-pad
// region) -> no kc/vc smem tiles -> 17.9 KB smem -> 8 CTAs/SM, ~1 wave.
// qT (transposed Q) + vk8 remain in smem. fp16 exact output.
// ---------------------------------------------------------------------------
#define QTS  68

__global__ __launch_bounds__(256) void attn_kernel(const unsigned char* __restrict__ spk,
                                                   __half* __restrict__ outp)
{
    __shared__ unsigned char qT[200 * QTS];
    __shared__ unsigned char vk8[64 * QTS];

    const int bx = blockIdx.x;
    const int t = bx >> 8;
    const int n = (bx >> 3) & 31;
    const int h = bx & 7;
    const int tid = threadIdx.x;
    const int warp = tid >> 5, lane = tid & 31;

    const size_t colOff = (size_t)(t * N_DIM + n) * L_DIM;
    const unsigned char* qg = spk + (size_t)(h * D_DIM) * NCOL + colOff;
    const unsigned char* kg = qg + (size_t)C_DIM * NCOL;
    const unsigned char* vg = qg + (size_t)2 * C_DIM * NCOL;

    // qT: 4x4 register byte transpose; 4 u32 loads -> 4 u32 stores
    for (int i = tid; i < 16 * 49; i += 256) {
        const int dg = (i / 49) * 4, w = i - (i / 49) * 49;
        const unsigned char* qp = qg + (size_t)dg * NCOL + 4 * w;
        const uint32_t q0 = *(const uint32_t*)(qp);
        const uint32_t q1 = *(const uint32_t*)(qp + NCOL);
        const uint32_t q2 = *(const uint32_t*)(qp + 2 * NCOL);
        const uint32_t q3 = *(const uint32_t*)(qp + 3 * NCOL);
#pragma unroll
        for (int j = 0; j < 4; j++) {
            const uint32_t sel = 0x0040u + 0x0011u * j;
            const uint32_t tl = __byte_perm(q0, q1, sel);
            const uint32_t th = __byte_perm(q2, q3, sel);
            *(uint32_t*)&qT[(4 * w + j) * QTS + dg] = __byte_perm(tl, th, 0x5410);
        }
    }
    for (int j = tid; j < 4 * 16; j += 256)
        *(uint32_t*)&qT[(196 + j / 16) * QTS + (j % 16) * 4] = 0;

    const int grp = lane >> 2;
    const int qd  = lane & 3;

    {   // Phase 1: vk[64d x 64e] = V.K^T, K=224, fragments straight from gmem.
        const int m0 = (warp & 3) * 16;
        const int ng = (warp >> 2) * 4;
        const unsigned char* vr0 = vg + (size_t)(m0 + grp) * NCOL;
        const unsigned char* vr1 = vr0 + (size_t)8 * NCOL;

        int c[4][4];
#pragma unroll
        for (int j = 0; j < 4; j++)
#pragma unroll
            for (int q = 0; q < 4; q++) c[j][q] = 0;

#pragma unroll
        for (int kt = 0; kt < 7; kt++) {
            const int kb  = kt * 32 + qd * 4;     // <= 204; valid u32 iff <= 192
            const int kb2 = kb + 16;
            uint32_t a[4];
            a[0] = (kb  <= 192) ? *(const uint32_t*)(vr0 + kb)  : 0u;
            a[1] = (kb  <= 192) ? *(const uint32_t*)(vr1 + kb)  : 0u;
            a[2] = (kb2 <= 192) ? *(const uint32_t*)(vr0 + kb2) : 0u;
            a[3] = (kb2 <= 192) ? *(const uint32_t*)(vr1 + kb2) : 0u;
#pragma unroll
            for (int j = 0; j < 4; j++) {
                const unsigned char* kr = kg + (size_t)((ng + j) * 8 + grp) * NCOL;
                const uint32_t b0 = (kb  <= 192) ? *(const uint32_t*)(kr + kb)  : 0u;
                const uint32_t b1 = (kb2 <= 192) ? *(const uint32_t*)(kr + kb2) : 0u;
                imma16832(c[j], a, b0, b1);
            }
        }
#pragma unroll
        for (int j = 0; j < 4; j++) {
            const int e0 = (ng + j) * 8 + qd * 2;
            *(unsigned short*)&vk8[(m0 + grp) * QTS + e0] =
                (unsigned short)((c[j][0] & 0xFF) | ((c[j][1] & 0xFF) << 8));
            *(unsigned short*)&vk8[(m0 + grp + 8) * QTS + e0] =
                (unsigned short)((c[j][2] & 0xFF) | ((c[j][3] & 0xFF) << 8));
        }
    }
    __syncthreads();

    {   // Phase 2: attn[64d x 196l] = 0.125 * vk . qT^T -> fp16 (exact)
        const int m0 = (warp & 3) * 16;
        const int hi = warp >> 2;
        const int jn0 = hi ? 13 : 0;
        const int cnt = hi ? 12 : 13;

        uint32_t a[2][4];
#pragma unroll
        for (int kt = 0; kt < 2; kt++) {
            const int kb = kt * 32 + qd * 4;
            a[kt][0] = *(const uint32_t*)&vk8[(m0 + grp) * QTS + kb];
            a[kt][1] = *(const uint32_t*)&vk8[(m0 + grp + 8) * QTS + kb];
            a[kt][2] = *(const uint32_t*)&vk8[(m0 + grp) * QTS + kb + 16];
            a[kt][3] = *(const uint32_t*)&vk8[(m0 + grp + 8) * QTS + kb + 16];
        }
        __half* orow0 = outp + (size_t)(h * D_DIM + m0 + grp) * NCOL + colOff;
        __half* orow1 = orow0 + (size_t)8 * NCOL;

#pragma unroll
        for (int i = 0; i < 13; i++) {
            if (i < cnt) {
                const int l0 = (jn0 + i) * 8;
                int c[4] = {0, 0, 0, 0};
#pragma unroll
                for (int kt = 0; kt < 2; kt++) {
                    const int kb = kt * 32 + qd * 4;
                    const uint32_t b0 = *(const uint32_t*)&qT[(l0 + grp) * QTS + kb];
                    const uint32_t b1 = *(const uint32_t*)&qT[(l0 + grp) * QTS + kb + 16];
                    imma16832(c, a[kt], b0, b1);
                }
                const int l = l0 + qd * 2;
                if (l + 1 < L_DIM) {
                    *(__half2*)&orow0[l] =
                        __floats2half2_rn((float)c[0] * 0.125f, (float)c[1] * 0.125f);
                    *(__half2*)&orow1[l] =
                        __floats2half2_rn((float)c[2] * 0.125f, (float)c[3] * 0.125f);
                }
            }
        }
    }
}

// ---------------------------------------------------------------------------
// Launch
// ---------------------------------------------------------------------------
extern "C" void kernel_launch(void* const* d_in, const int* in_sizes, int n_in,
                              void* d_out, int out_size)
{
    (void)in_sizes; (void)n_in; (void)out_size;
    const float* x_seq      = (const float*)d_in[0];
    const float* qkv_w      = (const float*)d_in[1];
    const float* qkv_gamma  = (const float*)d_in[2];
    const float* qkv_beta   = (const float*)d_in[3];
    const float* qkv_mean   = (const float*)d_in[4];
    const float* qkv_var    = (const float*)d_in[5];
    const float* proj_w     = (const float*)d_in[6];
    const float* proj_gamma = (const float*)d_in[7];
    const float* proj_beta  = (const float*)d_in[8];
    const float* proj_mean  = (const float*)d_in[9];
    const float* proj_var   = (const float*)d_in[10];
    float* out = (float*)d_out;

    __half *xh, *wq, *wp, *attnp, *attnh;
    unsigned char *qkvb;
    cudaGetSymbolAddress((void**)&xh, g_xh);
    cudaGetSymbolAddress((void**)&wq, g_wq);
    cudaGetSymbolAddress((void**)&wp, g_wp);
    cudaGetSymbolAddress((void**)&qkvb, g_qkvb);
    cudaGetSymbolAddress((void**)&attnp, g_attnp);
    cudaGetSymbolAddress((void**)&attnh, g_attnh);

    static bool attr_done = false;
    if (!attr_done) {
        cudaFuncSetAttribute(gemm_fused_kernel<0>,
                             cudaFuncAttributeMaxDynamicSharedMemorySize, DYN_SMEM);
        cudaFuncSetAttribute(gemm_fused_kernel<1>,
                             cudaFuncAttributeMaxDynamicSharedMemorySize, DYN_SMEM);
        attr_done = true;
    }

    // 0. Weight split (merged) + input conversion
    convert_w_kernel<<<((C3 + C_DIM) * K_DIM + 255) / 256, 256>>>(qkv_w, wq,
                                                                  proj_w, wp);
    {
        size_t tot = (size_t)B_DIM * K_DIM * (L_DIM / 4);
        convert_x_kernel<<<(unsigned)((tot + 255) / 256), 256>>>(
            (const float4*)x_seq, (uint2*)xh);
    }

    // 1. QKV GEMM + BN + LIF(1.0) -> u8 spikes
    dim3 g1(TSTRIDE / 32, C3 / OT);          // (196, 12)
    gemm_fused_kernel<0><<<g1, 256, DYN_SMEM>>>(wq, xh, qkv_gamma, qkv_beta,
                                                qkv_mean, qkv_var, qkvb, nullptr);
    // 2. Attention (int8 tensor cores, exact; direct-gmem operands)
    attn_kernel<<<T_DIM * N_DIM * H_DIM, 256>>>(qkvb, attnp);
    // 3. LIF (thr 0.5) -> fp16 spikes
    {
        const int total2 = C_DIM * TSTRIDE / 2;
        lif_mat_kernel<<<(total2 + 255) / 256, 256>>>((const __half2*)attnp,
                                                      (__half2*)attnh, total2, 0.5f);
    }
    // 4. Proj GEMM + BN + LIF(1.0) -> final f32 output
    dim3 g2(TSTRIDE / 32, C_DIM / OT);       // (196, 4)
    gemm_fused_kernel<1><<<g2, 256, DYN_SMEM>>>(wp, attnh, proj_gamma, proj_beta,
                                                proj_mean, proj_var, nullptr, out);
}

// round 17
// speedup vs baseline: 1.0273x; 1.0273x over previous
#include <cuda_runtime.h>
#include <cuda_fp16.h>
#include <cstdint>

#define T_DIM 4
#define N_DIM 32
#define C_DIM 512
#define L_DIM 196
#define H_DIM 8
#define D_DIM 64
#define C3 (3 * C_DIM)
#define B_DIM (T_DIM * N_DIM)     // 128
#define K_DIM 512
#define NCOL (B_DIM * L_DIM)      // 25088
#define TSTRIDE (N_DIM * L_DIM)   // 6272 = 196 * 32

// ---------------------------------------------------------------------------
// Scratch (device globals)
// ---------------------------------------------------------------------------
__device__ __half        g_xh   [(size_t)K_DIM * NCOL];
__device__ __half        g_wq   [(size_t)C3 * 1024];
__device__ __half        g_wp   [(size_t)C_DIM * 1024];
__device__ unsigned char g_qkvb [(size_t)C3 * NCOL];    // qkv spikes u8
__device__ __half        g_attnp[(size_t)C_DIM * NCOL]; // pre-LIF attn (fp16, exact)
__device__ __half        g_attnh[(size_t)C_DIM * NCOL]; // attn spikes fp16

// ---------------------------------------------------------------------------
// PTX helpers
// ---------------------------------------------------------------------------
__device__ __forceinline__ uint32_t smem_u32(const void* p) {
    return (uint32_t)__cvta_generic_to_shared(p);
}
__device__ __forceinline__ void cp_async16(uint32_t dst, const void* src) {
    asm volatile("cp.async.cg.shared.global [%0], [%1], 16;\n" :: "r"(dst), "l"(src));
}
__device__ __forceinline__ void cp_commit() {
    asm volatile("cp.async.commit_group;\n");
}
__device__ __forceinline__ void ldsm4(uint32_t (&r)[4], uint32_t addr) {
    asm volatile("ldmatrix.sync.aligned.m8n8.x4.shared.b16 {%0,%1,%2,%3}, [%4];"
                 : "=r"(r[0]), "=r"(r[1]), "=r"(r[2]), "=r"(r[3]) : "r"(addr));
}
__device__ __forceinline__ void ldsm4t(uint32_t (&r)[4], uint32_t addr) {
    asm volatile("ldmatrix.sync.aligned.m8n8.x4.trans.shared.b16 {%0,%1,%2,%3}, [%4];"
                 : "=r"(r[0]), "=r"(r[1]), "=r"(r[2]), "=r"(r[3]) : "r"(addr));
}
__device__ __forceinline__ void mma16816(float* d, const uint32_t* a, const uint32_t* b) {
    asm volatile("mma.sync.aligned.m16n8k16.row.col.f32.f16.f16.f32 "
                 "{%0,%1,%2,%3}, {%4,%5,%6,%7}, {%8,%9}, {%0,%1,%2,%3};"
                 : "+f"(d[0]), "+f"(d[1]), "+f"(d[2]), "+f"(d[3])
                 : "r"(a[0]), "r"(a[1]), "r"(a[2]), "r"(a[3]), "r"(b[0]), "r"(b[1]));
}
__device__ __forceinline__ void imma16832(int* c, const uint32_t* a, uint32_t b0, uint32_t b1) {
    asm volatile("mma.sync.aligned.m16n8k32.row.col.s32.u8.u8.s32 "
                 "{%0,%1,%2,%3}, {%4,%5,%6,%7}, {%8,%9}, {%0,%1,%2,%3};"
                 : "+r"(c[0]), "+r"(c[1]), "+r"(c[2]), "+r"(c[3])
                 : "r"(a[0]), "r"(a[1]), "r"(a[2]), "r"(a[3]), "r"(b0), "r"(b1));
}

// ---------------------------------------------------------------------------
// Conversions
// ---------------------------------------------------------------------------
__global__ void convert_x_kernel(const float4* __restrict__ x4, uint2* __restrict__ xh4) {
    const int L4 = L_DIM / 4;                      // 49
    const size_t total = (size_t)B_DIM * K_DIM * L4;
    size_t i = (size_t)blockIdx.x * blockDim.x + threadIdx.x;
    if (i >= total) return;
    const int l4 = (int)(i % L4);
    const int c  = (int)((i / L4) % K_DIM);
    const int b  = (int)(i / ((size_t)L4 * K_DIM));
    const float4 v = x4[i];
    const __half2 h01 = __floats2half2_rn(v.x, v.y);
    const __half2 h23 = __floats2half2_rn(v.z, v.w);
    uint2 o;
    o.x = *(const uint32_t*)&h01;
    o.y = *(const uint32_t*)&h23;
    xh4[((size_t)c * NCOL + b * L_DIM) / 4 + l4] = o;
}

// Merged W split for both weight matrices.
// Ws[o][(k/32)*64 + k%32] = hi, +32 = lo (hi + lo == W exactly in f32)
__global__ void convert_w_kernel(const float* __restrict__ wq, __half* __restrict__ wsq,
                                 const float* __restrict__ wp, __half* __restrict__ wsp) {
    int i = blockIdx.x * blockDim.x + threadIdx.x;
    const float* w; __half* ws;
    if (i < C3 * K_DIM) { w = wq; ws = wsq; }
    else {
        i -= C3 * K_DIM;
        if (i >= C_DIM * K_DIM) return;
        w = wp; ws = wsp;
    }
    const int k = i & (K_DIM - 1), o = i >> 9;
    const float v = w[i];
    const __half hi = __float2half(v);
    const __half lo = __float2half(v - __half2float(hi));
    const size_t base = (size_t)o * 1024 + (k >> 5) * 64 + (k & 31);
    ws[base] = hi;
    ws[base + 32] = lo;
}

// ---------------------------------------------------------------------------
// Fused tensor-core GEMM + BN + LIF (proven configuration).
// CTA tile: 128(M) x [32 elements x 4 timesteps](N) x 32(K), 256 threads,
// 8 warps each 32m x 64n. 2 CTAs/SM. STG=4, wait_group 2.
// ---------------------------------------------------------------------------
#define OT 128
#define KT 32
#define NSTAGE 16
#define STG 4
#define STG_BYTES (OT * 128 + 2 * KT * 128)   // 24576
#define DYN_SMEM (STG * STG_BYTES)            // 98304

template <int MODE>
__global__ __launch_bounds__(256, 2) void gemm_fused_kernel(
    const __half* __restrict__ Wsp,
    const __half* __restrict__ X,
    const float* __restrict__ gamma, const float* __restrict__ beta,
    const float* __restrict__ mean,  const float* __restrict__ var,
    unsigned char* __restrict__ outB, float* __restrict__ outF)
{
    extern __shared__ __half sm[];
    const uint32_t sBase = smem_u32(sm);

    const int o0 = blockIdx.y * OT;
    const int c0 = blockIdx.x * 32;
    const int tid  = threadIdx.x;
    const int warp = tid >> 5, lane = tid & 31;
    const int wm = warp & 3, wn = warp >> 2;

    const int wrow = tid >> 1;
    const int wcb  = (tid & 1) * 4;
    const int xrow = tid >> 3;
    const int xq   = tid & 7;

    float acc[2][8][4];
#pragma unroll
    for (int a = 0; a < 2; a++)
#pragma unroll
        for (int n = 0; n < 8; n++)
#pragma unroll
            for (int j = 0; j < 4; j++) acc[a][n][j] = 0.f;

    auto issue = [&](int s) {
        const uint32_t sb = sBase + (uint32_t)(s & (STG - 1)) * STG_BYTES;
        const __half* wsrc = Wsp + (size_t)(o0 + wrow) * 1024 + s * 64;
        const uint32_t wdst = sb + wrow * 128;
#pragma unroll
        for (int i = 0; i < 4; i++) {
            int ch = wcb + i;
            cp_async16(wdst + ((ch ^ (wrow & 7)) << 4), wsrc + ch * 8);
        }
#pragma unroll
        for (int cc = 0; cc < 2; cc++) {
            const int c = xq + cc * 8;
            const __half* xsrc = X + (size_t)(s * KT + xrow) * NCOL +
                                 (size_t)(c >> 2) * TSTRIDE + c0 + (c & 3) * 8;
            const uint32_t xdst = sb + OT * 128 + (c >> 3) * 4096 + xrow * 128 +
                                  (((c & 7) ^ (xrow & 7)) << 4);
            cp_async16(xdst, xsrc);
        }
        cp_commit();
    };

    issue(0); issue(1); issue(2);

    const int lrow = lane & 15;
    const int lch  = lane >> 4;

#pragma unroll
    for (int s = 0; s < NSTAGE; s++) {
        const int rem = NSTAGE - 1 - s;
        if (rem >= 2)      asm volatile("cp.async.wait_group 2;\n");
        else if (rem == 1) asm volatile("cp.async.wait_group 1;\n");
        else               asm volatile("cp.async.wait_group 0;\n");
        __syncthreads();

        if (s + 3 < NSTAGE) issue(s + 3);

        const uint32_t sWb = sBase + (uint32_t)(s & (STG - 1)) * STG_BYTES;
        const uint32_t sXb = sWb + OT * 128 + wn * 4096;

#pragma unroll
        for (int s2 = 0; s2 < 2; s2++) {
            uint32_t Bf[4][4];
#pragma unroll
            for (int i = 0; i < 4; i++) {
                int rowB = s2 * 16 + lrow;
                int ch = i * 2 + lch;
                ldsm4t(Bf[i], sXb + rowB * 128 + ((ch ^ (rowB & 7)) << 4));
            }
#pragma unroll
            for (int p = 0; p < 2; p++) {
                uint32_t Af[2][4];
                const int kcol = p * 32 + s2 * 16;
#pragma unroll
                for (int mf = 0; mf < 2; mf++) {
                    int m = wm * 32 + mf * 16 + lrow;
                    int ch = (kcol >> 3) + lch;
                    ldsm4(Af[mf], sWb + m * 128 + ((ch ^ (m & 7)) << 4));
                }
#pragma unroll
                for (int mf = 0; mf < 2; mf++)
#pragma unroll
                    for (int nf = 0; nf < 8; nf++)
                        mma16816(acc[mf][nf], Af[mf], &Bf[nf >> 1][(nf & 1) * 2]);
            }
        }
    }

    // ---- Epilogue: BN -> smem bounce -> LIF over t -> store ----
    __syncthreads();
    float* smf = (float*)sm;   // [128][132]

#pragma unroll
    for (int mf = 0; mf < 2; mf++) {
#pragma unroll
        for (int dd = 0; dd < 2; dd++) {
            const int m = wm * 32 + mf * 16 + dd * 8 + (lane >> 2);
            const int o = o0 + m;
            const float inv  = __ldg(&gamma[o]) * rsqrtf(__ldg(&var[o]) + 1e-5f);
            const float bias = __ldg(&beta[o]) - __ldg(&mean[o]) * inv;
#pragma unroll
            for (int nf = 0; nf < 8; nf++) {
                const int j = wn * 64 + nf * 8 + (lane & 3) * 2;
                smf[m * 132 + j]     = acc[mf][nf][dd * 2 + 0] * inv + bias;
                smf[m * 132 + j + 1] = acc[mf][nf][dd * 2 + 1] * inv + bias;
            }
        }
    }
    __syncthreads();

    const int e = tid & 31;
#pragma unroll 1
    for (int pass = 0; pass < 16; pass++) {
        const int m = pass * 8 + (tid >> 5);
        const float* r = &smf[m * 132];
        float v = 0.f;
        if (MODE == 0) {
            unsigned char* dst = outB + (size_t)(o0 + m) * NCOL + c0 + e;
#pragma unroll
            for (int t = 0; t < T_DIM; t++) {
                const float x = r[t * 32 + e];
                v += 0.5f * (x - v);
                const float s = (v >= 1.0f) ? 1.f : 0.f;
                dst[(size_t)t * TSTRIDE] = (unsigned char)s;
                v *= (1.f - s);
            }
        } else {
            const int g = c0 + e;
            const int n = g / L_DIM, l = g - n * L_DIM;
#pragma unroll
            for (int t = 0; t < T_DIM; t++) {
                const float x = r[t * 32 + e];
                v += 0.5f * (x - v);
                const float s = (v >= 1.0f) ? 1.f : 0.f;
                outF[(((size_t)(t * N_DIM + n)) * C_DIM + (o0 + m)) * L_DIM + l] = s;
                v *= (1.f - s);
            }
        }
    }
}

// ---------------------------------------------------------------------------
// LIF (decay 0.5, thr 0.5) for attn: fp16 pre-LIF in (exact), fp16 spikes out.
// ---------------------------------------------------------------------------
__global__ void lif_mat_kernel(const __half2* __restrict__ in, __half2* __restrict__ out,
                               int total2, float thr)
{
    const int i = blockIdx.x * blockDim.x + threadIdx.x;
    if (i >= total2) return;
    const int half_ts = TSTRIDE / 2;
    const int o = i / half_ts, r = i % half_ts;
    const size_t base2 = ((size_t)o * NCOL) / 2 + r;
    float v0 = 0.f, v1 = 0.f;
#pragma unroll
    for (int t = 0; t < T_DIM; t++) {
        const float2 x = __half22float2(in[base2 + (size_t)t * half_ts]);
        v0 += 0.5f * (x.x - v0);
        v1 += 0.5f * (x.y - v1);
        const float s0 = (v0 >= thr) ? 1.f : 0.f;
        const float s1 = (v1 >= thr) ? 1.f : 0.f;
        out[base2 + (size_t)t * half_ts] = __floats2half2_rn(s0, s1);
        v0 *= (1.f - s0);
        v1 *= (1.f - s1);
    }
}

// ---------------------------------------------------------------------------
// Attention per (t, n, h) on int8 tensor cores. Conflict-free smem layout
// (KPAD=240, QTS=80) placed in DYNAMIC shared memory (51840 B > 48KB static
// limit). u8 spikes in, fp16 exact out.
// ---------------------------------------------------------------------------
#define KPAD 240
#define QTS  80
#define ATTN_KC   0
#define ATTN_VC   (64 * KPAD)                 // 15360
#define ATTN_QT   (2 * 64 * KPAD)             // 30720
#define ATTN_VK8  (2 * 64 * KPAD + 200 * QTS) // 46720
#define ATTN_SMEM (ATTN_VK8 + 64 * QTS)       // 51840

__global__ __launch_bounds__(256) void attn_kernel(const unsigned char* __restrict__ spk,
                                                   __half* __restrict__ outp)
{
    extern __shared__ unsigned char smem_attn[];
    unsigned char* kc  = smem_attn + ATTN_KC;
    unsigned char* vc  = smem_attn + ATTN_VC;
    unsigned char* qT  = smem_attn + ATTN_QT;
    unsigned char* vk8 = smem_attn + ATTN_VK8;

    const int bx = blockIdx.x;
    const int t = bx >> 8;
    const int n = (bx >> 3) & 31;
    const int h = bx & 7;
    const int tid = threadIdx.x;
    const int warp = tid >> 5, lane = tid & 31;

    const size_t colOff = (size_t)(t * N_DIM + n) * L_DIM;
    const unsigned char* qg = spk + (size_t)(h * D_DIM) * NCOL + colOff;
    const unsigned char* kg = qg + (size_t)C_DIM * NCOL;
    const unsigned char* vg = qg + (size_t)2 * C_DIM * NCOL;

    // k/v: straight u32 row copies (196 B = 49 u32 per row)
    for (int i = tid; i < 64 * 49; i += 256) {
        const int d = i / 49, w = i - d * 49;
        const size_t a = (size_t)d * NCOL + 4 * w;
        *(uint32_t*)&kc[d * KPAD + 4 * w] = *(const uint32_t*)(kg + a);
        *(uint32_t*)&vc[d * KPAD + 4 * w] = *(const uint32_t*)(vg + a);
    }
    // qT: 4x4 register byte transpose; 4 u32 loads -> 4 u32 stores
    for (int i = tid; i < 16 * 49; i += 256) {
        const int dg = (i / 49) * 4, w = i - (i / 49) * 49;
        const unsigned char* qp = qg + (size_t)dg * NCOL + 4 * w;
        const uint32_t q0 = *(const uint32_t*)(qp);
        const uint32_t q1 = *(const uint32_t*)(qp + NCOL);
        const uint32_t q2 = *(const uint32_t*)(qp + 2 * NCOL);
        const uint32_t q3 = *(const uint32_t*)(qp + 3 * NCOL);
#pragma unroll
        for (int j = 0; j < 4; j++) {
            const uint32_t sel = 0x0040u + 0x0011u * j;
            const uint32_t tl = __byte_perm(q0, q1, sel);
            const uint32_t th = __byte_perm(q2, q3, sel);
            *(uint32_t*)&qT[(4 * w + j) * QTS + dg] = __byte_perm(tl, th, 0x5410);
        }
    }
    // zero pads: kc/vc cols 196..239 (11 u32 per row), qT rows 196..199
    for (int j = tid; j < 64 * 11; j += 256) {
        const int d = j / 11, c = 196 + (j % 11) * 4;
        *(uint32_t*)&kc[d * KPAD + c] = 0;
        *(uint32_t*)&vc[d * KPAD + c] = 0;
    }
    for (int j = tid; j < 4 * 16; j += 256)
        *(uint32_t*)&qT[(196 + j / 16) * QTS + (j % 16) * 4] = 0;
    __syncthreads();

    const int grp = lane >> 2;
    const int qd  = lane & 3;

    {   // Phase 1: vk[64d x 64e] = V.K^T, K=224
        const int m0 = (warp & 3) * 16;
        const int ng = (warp >> 2) * 4;
        int c[4][4];
#pragma unroll
        for (int j = 0; j < 4; j++)
#pragma unroll
            for (int q = 0; q < 4; q++) c[j][q] = 0;

#pragma unroll
        for (int kt = 0; kt < 7; kt++) {
            uint32_t a[4];
            const int kb = kt * 32 + qd * 4;
            a[0] = *(const uint32_t*)&vc[(m0 + grp) * KPAD + kb];
            a[1] = *(const uint32_t*)&vc[(m0 + grp + 8) * KPAD + kb];
            a[2] = *(const uint32_t*)&vc[(m0 + grp) * KPAD + kb + 16];
            a[3] = *(const uint32_t*)&vc[(m0 + grp + 8) * KPAD + kb + 16];
#pragma unroll
            for (int j = 0; j < 4; j++) {
                const int e0 = (ng + j) * 8;
                const uint32_t b0 = *(const uint32_t*)&kc[(e0 + grp) * KPAD + kb];
                const uint32_t b1 = *(const uint32_t*)&kc[(e0 + grp) * KPAD + kb + 16];
                imma16832(c[j], a, b0, b1);
            }
        }
#pragma unroll
        for (int j = 0; j < 4; j++) {
            const int e0 = (ng + j) * 8 + qd * 2;
            *(unsigned short*)&vk8[(m0 + grp) * QTS + e0] =
                (unsigned short)((c[j][0] & 0xFF) | ((c[j][1] & 0xFF) << 8));
            *(unsigned short*)&vk8[(m0 + grp + 8) * QTS + e0] =
                (unsigned short)((c[j][2] & 0xFF) | ((c[j][3] & 0xFF) << 8));
        }
    }
    __syncthreads();

    {   // Phase 2: attn[64d x 196l] = 0.125 * vk . qT^T -> fp16 (exact)
        const int m0 = (warp & 3) * 16;
        const int hi = warp >> 2;
        const int jn0 = hi ? 13 : 0;
        const int cnt = hi ? 12 : 13;

        uint32_t a[2][4];
#pragma unroll
        for (int kt = 0; kt < 2; kt++) {
            const int kb = kt * 32 + qd * 4;
            a[kt][0] = *(const uint32_t*)&vk8[(m0 + grp) * QTS + kb];
            a[kt][1] = *(const uint32_t*)&vk8[(m0 + grp + 8) * QTS + kb];
            a[kt][2] = *(const uint32_t*)&vk8[(m0 + grp) * QTS + kb + 16];
            a[kt][3] = *(const uint32_t*)&vk8[(m0 + grp + 8) * QTS + kb + 16];
        }
        __half* orow0 = outp + (size_t)(h * D_DIM + m0 + grp) * NCOL + colOff;
        __half* orow1 = orow0 + (size_t)8 * NCOL;

#pragma unroll
        for (int i = 0; i < 13; i++) {
            if (i < cnt) {
                const int l0 = (jn0 + i) * 8;
                int c[4] = {0, 0, 0, 0};
#pragma unroll
                for (int kt = 0; kt < 2; kt++) {
                    const int kb = kt * 32 + qd * 4;
                    const uint32_t b0 = *(const uint32_t*)&qT[(l0 + grp) * QTS + kb];
                    const uint32_t b1 = *(const uint32_t*)&qT[(l0 + grp) * QTS + kb + 16];
                    imma16832(c, a[kt], b0, b1);
                }
                const int l = l0 + qd * 2;
                if (l + 1 < L_DIM) {
                    *(__half2*)&orow0[l] =
                        __floats2half2_rn((float)c[0] * 0.125f, (float)c[1] * 0.125f);
                    *(__half2*)&orow1[l] =
                        __floats2half2_rn((float)c[2] * 0.125f, (float)c[3] * 0.125f);
                }
            }
        }
    }
}

// ---------------------------------------------------------------------------
// Launch
// ---------------------------------------------------------------------------
extern "C" void kernel_launch(void* const* d_in, const int* in_sizes, int n_in,
                              void* d_out, int out_size)
{
    (void)in_sizes; (void)n_in; (void)out_size;
    const float* x_seq      = (const float*)d_in[0];
    const float* qkv_w      = (const float*)d_in[1];
    const float* qkv_gamma  = (const float*)d_in[2];
    const float* qkv_beta   = (const float*)d_in[3];
    const float* qkv_mean   = (const float*)d_in[4];
    const float* qkv_var    = (const float*)d_in[5];
    const float* proj_w     = (const float*)d_in[6];
    const float* proj_gamma = (const float*)d_in[7];
    const float* proj_beta  = (const float*)d_in[8];
    const float* proj_mean  = (const float*)d_in[9];
    const float* proj_var   = (const float*)d_in[10];
    float* out = (float*)d_out;

    __half *xh, *wq, *wp, *attnp, *attnh;
    unsigned char *qkvb;
    cudaGetSymbolAddress((void**)&xh, g_xh);
    cudaGetSymbolAddress((void**)&wq, g_wq);
    cudaGetSymbolAddress((void**)&wp, g_wp);
    cudaGetSymbolAddress((void**)&qkvb, g_qkvb);
    cudaGetSymbolAddress((void**)&attnp, g_attnp);
    cudaGetSymbolAddress((void**)&attnh, g_attnh);

    static bool attr_done = false;
    if (!attr_done) {
        cudaFuncSetAttribute(gemm_fused_kernel<0>,
                             cudaFuncAttributeMaxDynamicSharedMemorySize, DYN_SMEM);
        cudaFuncSetAttribute(gemm_fused_kernel<1>,
                             cudaFuncAttributeMaxDynamicSharedMemorySize, DYN_SMEM);
        cudaFuncSetAttribute(attn_kernel,
                             cudaFuncAttributeMaxDynamicSharedMemorySize, ATTN_SMEM);
        attr_done = true;
    }

    // 0. Weight split (merged) + input conversion
    convert_w_kernel<<<((C3 + C_DIM) * K_DIM + 255) / 256, 256>>>(qkv_w, wq,
                                                                  proj_w, wp);
    {
        size_t tot = (size_t)B_DIM * K_DIM * (L_DIM / 4);
        convert_x_kernel<<<(unsigned)((tot + 255) / 256), 256>>>(
            (const float4*)x_seq, (uint2*)xh);
    }

    // 1. QKV GEMM + BN + LIF(1.0) -> u8 spikes
    dim3 g1(TSTRIDE / 32, C3 / OT);          // (196, 12)
    gemm_fused_kernel<0><<<g1, 256, DYN_SMEM>>>(wq, xh, qkv_gamma, qkv_beta,
                                                qkv_mean, qkv_var, qkvb, nullptr);
    // 2. Attention (int8 tensor cores, exact; conflict-free smem layout)
    attn_kernel<<<T_DIM * N_DIM * H_DIM, 256, ATTN_SMEM>>>(qkvb, attnp);
    // 3. LIF (thr 0.5) -> fp16 spikes
    {
        const int total2 = C_DIM * TSTRIDE / 2;
        lif_mat_kernel<<<(total2 + 255) / 256, 256>>>((const __half2*)attnp,
                                                      (__half2*)attnh, total2, 0.5f);
    }
    // 4. Proj GEMM + BN + LIF(1.0) -> final f32 output
    dim3 g2(TSTRIDE / 32, C_DIM / OT);       // (196, 4)
    gemm_fused_kernel<1><<<g2, 256, DYN_SMEM>>>(wp, attnh, proj_gamma, proj_beta,
                                                proj_mean, proj_var, nullptr, out);
}